// round 12
// baseline (speedup 1.0000x reference)
#include <cuda_runtime.h>
#include <cuda_fp16.h>
#include <cstdint>
#include <math.h>

#define BATCH 32
#define SEQ   4096
#define UNITS 1024
#define M_TOTAL (BATCH * SEQ)      // 131072
#define NBLK  8
#define KC    64
#define NCHUNK 16
#define STAGES 3
#define CTAM  256                  // CTA M rows
#define TILE_A (CTAM * 128)        // 32768 B (256 rows x 128B)
#define TILE_BT (128 * 128)        // 16384 B (128 rows x 128B)
#define STAGE_B (TILE_A + TILE_BT) // 49152
#define SMEM_GEMM (STAGES * STAGE_B + 3072)   // 150528

// ---------------------------------------------------------------------------
// Scratch
// ---------------------------------------------------------------------------
__device__ __half g_Ah[(size_t)M_TOTAL * UNITS];
__device__ __half g_Bh[(size_t)UNITS * UNITS];     // U_w^T [n][k] fp16
__device__ float g_wsb[BATCH * UNITS];
__device__ float g_score_part[(size_t)M_TOTAL * NBLK];
__device__ float g_ctx_part[BATCH * 8 * UNITS];

// ---------------------------------------------------------------------------
// PTX helpers
// ---------------------------------------------------------------------------
__device__ __forceinline__ uint32_t smem_u32(const void* p) {
    uint32_t a;
    asm("{ .reg .u64 t; cvta.to.shared.u64 t, %1; cvt.u32.u64 %0, t; }" : "=r"(a) : "l"(p));
    return a;
}
__device__ __forceinline__ void cp16(uint32_t dst, const void* src) {
    asm volatile("cp.async.cg.shared.global [%0], [%1], 16;"
                 :: "r"(dst), "l"(__cvta_generic_to_global(src)) : "memory");
}
#define CP_COMMIT() asm volatile("cp.async.commit_group;" ::: "memory")
#define CP_WAIT(n)  asm volatile("cp.async.wait_group %0;" :: "n"(n) : "memory")

__device__ __forceinline__ void ldsm4(uint32_t r[4], uint32_t addr) {
    asm volatile("ldmatrix.sync.aligned.m8n8.x4.shared.b16 {%0,%1,%2,%3}, [%4];"
                 : "=r"(r[0]), "=r"(r[1]), "=r"(r[2]), "=r"(r[3]) : "r"(addr));
}
__device__ __forceinline__ void mma_f16(float c[4], const uint32_t a[4],
                                        uint32_t b0, uint32_t b1) {
    asm volatile(
        "mma.sync.aligned.m16n8k16.row.col.f32.f16.f16.f32 "
        "{%0,%1,%2,%3}, {%4,%5,%6,%7}, {%8,%9}, {%0,%1,%2,%3};"
        : "+f"(c[0]), "+f"(c[1]), "+f"(c[2]), "+f"(c[3])
        : "r"(a[0]), "r"(a[1]), "r"(a[2]), "r"(a[3]), "r"(b0), "r"(b1));
}

// SW128 swizzle: (row, 16B-chunk c), c in 0..7
__device__ __forceinline__ uint32_t swz128(int row, int c) {
    return (uint32_t)(row * 128 + ((c ^ (row & 7)) << 4));
}

// fast tanh: 1 - 2/(exp(2x)+1)
__device__ __forceinline__ float ftanh(float x) {
    float e2 = __expf(2.f * x);
    return 1.f - __fdividef(2.f, e2 + 1.f);
}

// ---------------------------------------------------------------------------
// Prep: hidden fp32 -> fp16
// ---------------------------------------------------------------------------
__global__ void convA_kernel(const float* __restrict__ A) {
    size_t i = ((size_t)blockIdx.x * 256 + threadIdx.x) * 8;
    float4 v0 = *(const float4*)(A + i);
    float4 v1 = *(const float4*)(A + i + 4);
    __half h[8];
    float f[8] = {v0.x, v0.y, v0.z, v0.w, v1.x, v1.y, v1.z, v1.w};
    #pragma unroll
    for (int q = 0; q < 8; q++) h[q] = __float2half_rn(f[q]);
    *(uint4*)(g_Ah + i) = *(uint4*)h;
}

// ---------------------------------------------------------------------------
// Prep: U_w [k][n] fp32 -> transposed fp16 [n][k]
// ---------------------------------------------------------------------------
__global__ void convB_kernel(const float* __restrict__ U) {
    __shared__ float t[32][33];
    int n0 = blockIdx.x * 32, k0 = blockIdx.y * 32;
    t[threadIdx.y][threadIdx.x] = U[(size_t)(k0 + threadIdx.y) * UNITS + n0 + threadIdx.x];
    __syncthreads();
    float v = t[threadIdx.x][threadIdx.y];
    g_Bh[(size_t)(n0 + threadIdx.y) * UNITS + k0 + threadIdx.x] = __float2half_rn(v);
}

// ---------------------------------------------------------------------------
// Prep: wsb = s_prev@W_w + W_b + U_b
// ---------------------------------------------------------------------------
__global__ void ws_kernel(const float* __restrict__ s_prev,
                          const float* __restrict__ W_w,
                          const float* __restrict__ W_b,
                          const float* __restrict__ U_b) {
    __shared__ float srow[UNITS];
    int b = blockIdx.x, v = threadIdx.x;
    srow[v] = s_prev[b * UNITS + v];
    __syncthreads();
    float a0 = 0.f, a1 = 0.f, a2 = 0.f, a3 = 0.f;
    #pragma unroll 4
    for (int k = 0; k < UNITS; k += 4) {
        a0 += srow[k + 0] * W_w[(size_t)(k + 0) * UNITS + v];
        a1 += srow[k + 1] * W_w[(size_t)(k + 1) * UNITS + v];
        a2 += srow[k + 2] * W_w[(size_t)(k + 2) * UNITS + v];
        a3 += srow[k + 3] * W_w[(size_t)(k + 3) * UNITS + v];
    }
    g_wsb[b * UNITS + v] = (a0 + a1) + (a2 + a3) + W_b[v] + U_b[v];
}

// ---------------------------------------------------------------------------
// GEMM: 256x128 CTA tile, 8 warps (4m x 2n), warp tile 64x64.
// fp16 single-term, KC=64 chunks, 3-stage cp.async, fast-tanh·V epilogue.
// grid = (NBLK, 512), block = 256, 1 CTA/SM.
// ---------------------------------------------------------------------------
__global__ __launch_bounds__(256, 1)
void score_gemm_mma(const float* __restrict__ V) {
    extern __shared__ char smem[];
    float* Ws = (float*)(smem + STAGES * STAGE_B);   // [128]
    float* Vs = Ws + 128;                             // [128]
    float (*sc_s)[2] = (float(*)[2])(Vs + 128);       // [256][2] = 2048 B

    const int nt    = blockIdx.x;
    const int mtile = blockIdx.y;        // 0..511 (256 rows each)
    const int tid   = threadIdx.x;
    const int lane  = tid & 31;
    const int wid   = tid >> 5;
    const int wm    = wid & 3;           // m quarter (64 rows)
    const int wn    = wid >> 2;          // n half (64 cols)
    const int b     = mtile >> 4;        // 16 CTAs of 256 rows per batch
    const uint32_t sbase = smem_u32(smem);

    if (tid < 128) {
        Ws[tid] = g_wsb[b * UNITS + nt * 128 + tid];
        Vs[tid] = V[nt * 128 + tid];
    }

    float acc[4][8][4];
    #pragma unroll
    for (int mi = 0; mi < 4; mi++)
        #pragma unroll
        for (int nf = 0; nf < 8; nf++)
            #pragma unroll
            for (int q = 0; q < 4; q++)
                acc[mi][nf][q] = 0.f;

    // --- cp.async geometry: 3072 16B-segments per stage, 12 per thread ---
    // j<8 -> A tile (2048 segs), j>=8 -> B tile (1024 segs)
    const __half* baseA = g_Ah + (size_t)mtile * CTAM * UNITS;
    const __half* baseB = g_Bh + (size_t)nt * 128 * UNITS;
    uint32_t cp_off[12];
    int      gOff[12];
    #pragma unroll
    for (int j = 0; j < 12; j++) {
        int s = tid + j * 256;
        if (s < 2048) {
            int row = s >> 3, c = s & 7;
            cp_off[j] = swz128(row, c);
            gOff[j]   = row * UNITS + c * 8;
        } else {
            int s2 = s - 2048;
            int row = s2 >> 3, c = s2 & 7;
            cp_off[j] = TILE_A + swz128(row, c);
            gOff[j]   = row * UNITS + c * 8;
        }
    }

    // --- ldsm fragment bases ---
    const int a_row_off = ((lane >> 3) & 1) * 8 + (lane & 7);
    const int k_sub     = lane >> 4;          // 0/1
    const int b_row_off = lane & 15;
    const int r7a = a_row_off & 7;
    const int r7b = b_row_off & 7;
    uint32_t rbA[4], rbB[4];
    #pragma unroll
    for (int mi = 0; mi < 4; mi++)
        rbA[mi] = (uint32_t)((wm * 64 + mi * 16 + a_row_off) * 128);
    #pragma unroll
    for (int p = 0; p < 4; p++)
        rbB[p] = (uint32_t)(TILE_A + (wn * 64 + p * 16 + b_row_off) * 128);

    // prologue: 2 stages in flight (chunks 0, 1)
    #pragma unroll
    for (int st0 = 0; st0 < 2; st0++) {
        uint32_t sb = sbase + st0 * STAGE_B;
        #pragma unroll
        for (int j = 0; j < 12; j++) {
            const __half* src = (j < 8 ? baseA : baseB) + gOff[j] + st0 * KC;
            cp16(sb + cp_off[j], src);
        }
        CP_COMMIT();
    }

    int cons = 0, prod = 2;
    for (int kc = 0; kc < NCHUNK; kc++) {
        CP_WAIT(1);
        __syncthreads();
        if (kc + 2 < NCHUNK) {
            uint32_t sb = sbase + prod * STAGE_B;
            #pragma unroll
            for (int j = 0; j < 12; j++) {
                const __half* src = (j < 8 ? baseA : baseB) + gOff[j] + (kc + 2) * KC;
                cp16(sb + cp_off[j], src);
            }
        }
        CP_COMMIT();

        const uint32_t st = sbase + cons * STAGE_B;
        uint32_t aAddr[4], bAddr[4];
        #pragma unroll
        for (int mi = 0; mi < 4; mi++) aAddr[mi] = st + rbA[mi];
        #pragma unroll
        for (int p = 0; p < 4; p++)   bAddr[p]  = st + rbB[p];

        #pragma unroll
        for (int ks = 0; ks < 4; ks++) {
            const int kk = (ks << 1) | k_sub;
            const uint32_t xA = (uint32_t)((kk ^ r7a) << 4);
            const uint32_t xB = (uint32_t)((kk ^ r7b) << 4);
            uint32_t a[4][4];
            #pragma unroll
            for (int mi = 0; mi < 4; mi++)
                ldsm4(a[mi], aAddr[mi] + xA);
            #pragma unroll
            for (int p = 0; p < 4; p++) {
                uint32_t bb[4];
                ldsm4(bb, bAddr[p] + xB);
                #pragma unroll
                for (int mi = 0; mi < 4; mi++) {
                    mma_f16(acc[mi][2 * p],     a[mi], bb[0], bb[2]);
                    mma_f16(acc[mi][2 * p + 1], a[mi], bb[1], bb[3]);
                }
            }
        }
        cons = (cons == 2) ? 0 : cons + 1;
        prod = (prod == 2) ? 0 : prod + 1;
    }

    // ---- epilogue: per-warp 64-row x 64-col partial scores ----
    const int tc = (lane & 3) * 2;
    #pragma unroll
    for (int mi = 0; mi < 4; mi++) {
        float s0 = 0.f, s1 = 0.f;
        #pragma unroll
        for (int nf = 0; nf < 8; nf++) {
            int n = wn * 64 + nf * 8 + tc;
            float w0 = Ws[n], w1 = Ws[n + 1];
            float v0 = Vs[n], v1 = Vs[n + 1];
            s0 += v0 * ftanh(w0 + acc[mi][nf][0]) + v1 * ftanh(w1 + acc[mi][nf][1]);
            s1 += v0 * ftanh(w0 + acc[mi][nf][2]) + v1 * ftanh(w1 + acc[mi][nf][3]);
        }
        s0 += __shfl_xor_sync(0xffffffffu, s0, 1);
        s0 += __shfl_xor_sync(0xffffffffu, s0, 2);
        s1 += __shfl_xor_sync(0xffffffffu, s1, 1);
        s1 += __shfl_xor_sync(0xffffffffu, s1, 2);
        if ((lane & 3) == 0) {
            int r = wm * 64 + mi * 16 + (lane >> 2);
            sc_s[r][wn]     = s0;
            sc_s[r + 8][wn] = s1;
        }
    }
    __syncthreads();
    g_score_part[((size_t)mtile * CTAM + tid) * NBLK + nt] =
        sc_s[tid][0] + sc_s[tid][1];
}

// ---------------------------------------------------------------------------
// Softmax (sums NBLK partials + V_b), writes weights.
// ---------------------------------------------------------------------------
__global__ void softmax_kernel(float* __restrict__ weights_out,
                               const float* __restrict__ V_b) {
    __shared__ float red[1024];
    const int b = blockIdx.x, t = threadIdx.x;
    const float vb = V_b[0];

    float sc[4];
    float mx = -1e30f;
    #pragma unroll
    for (int j = 0; j < 4; j++) {
        int s = t + j * 1024;
        const float* p = &g_score_part[(size_t)(b * SEQ + s) * NBLK];
        float v = vb;
        #pragma unroll
        for (int q = 0; q < NBLK; q++) v += p[q];
        sc[j] = v;
        mx = fmaxf(mx, v);
    }
    red[t] = mx;
    __syncthreads();
    for (int o = 512; o > 0; o >>= 1) {
        if (t < o) red[t] = fmaxf(red[t], red[t + o]);
        __syncthreads();
    }
    mx = red[0];
    __syncthreads();

    float e[4], sum = 0.f;
    #pragma unroll
    for (int j = 0; j < 4; j++) { e[j] = expf(sc[j] - mx); sum += e[j]; }
    red[t] = sum;
    __syncthreads();
    for (int o = 512; o > 0; o >>= 1) {
        if (t < o) red[t] += red[t + o];
        __syncthreads();
    }
    float inv = 1.f / red[0];
    #pragma unroll
    for (int j = 0; j < 4; j++)
        weights_out[b * SEQ + t + j * 1024] = e[j] * inv;
}

// ---------------------------------------------------------------------------
// Context: weighted sum over S, reading fp16 g_Ah.
// ---------------------------------------------------------------------------
__global__ void ctx_partial_kernel(const float* __restrict__ W) {
    const int b = blockIdx.x, cs = blockIdx.y, u = threadIdx.x;
    const float* w = W + b * SEQ + cs * 512;
    const __half* h = g_Ah + ((size_t)b * SEQ + cs * 512) * UNITS + u;
    float a0 = 0.f, a1 = 0.f, a2 = 0.f, a3 = 0.f;
    for (int s = 0; s < 512; s += 4) {
        a0 += w[s + 0] * __half2float(h[(size_t)(s + 0) * UNITS]);
        a1 += w[s + 1] * __half2float(h[(size_t)(s + 1) * UNITS]);
        a2 += w[s + 2] * __half2float(h[(size_t)(s + 2) * UNITS]);
        a3 += w[s + 3] * __half2float(h[(size_t)(s + 3) * UNITS]);
    }
    g_ctx_part[(b * 8 + cs) * UNITS + u] = (a0 + a1) + (a2 + a3);
}

__global__ void ctx_reduce_kernel(float* __restrict__ ctx_out) {
    const int b = blockIdx.x, u = threadIdx.x;
    float acc = 0.f;
    #pragma unroll
    for (int cs = 0; cs < 8; cs++)
        acc += g_ctx_part[(b * 8 + cs) * UNITS + u];
    ctx_out[b * UNITS + u] = acc;
}

// ---------------------------------------------------------------------------
extern "C" void kernel_launch(void* const* d_in, const int* in_sizes, int n_in,
                              void* d_out, int out_size) {
    const float* s_prev = (const float*)d_in[0];
    const float* hidden = (const float*)d_in[1];
    const float* W_w    = (const float*)d_in[2];
    const float* W_b    = (const float*)d_in[3];
    const float* U_w    = (const float*)d_in[4];
    const float* U_b    = (const float*)d_in[5];
    const float* V_w    = (const float*)d_in[6];
    const float* V_b    = (const float*)d_in[7];

    float* out     = (float*)d_out;
    float* ctx_out = out;                      // [32,1024]
    float* w_out   = out + BATCH * UNITS;      // [32,4096,1]

    cudaFuncSetAttribute(score_gemm_mma,
        cudaFuncAttributeMaxDynamicSharedMemorySize, SMEM_GEMM);

    convA_kernel<<<(unsigned)((size_t)M_TOTAL * UNITS / 2048), 256>>>(hidden);
    convB_kernel<<<dim3(32, 32), dim3(32, 32)>>>(U_w);
    ws_kernel<<<BATCH, UNITS>>>(s_prev, W_w, W_b, U_b);
    score_gemm_mma<<<dim3(NBLK, M_TOTAL / CTAM), 256, SMEM_GEMM>>>(V_w);
    softmax_kernel<<<BATCH, 1024>>>(w_out, V_b);
    ctx_partial_kernel<<<dim3(BATCH, 8), 1024>>>(w_out);
    ctx_reduce_kernel<<<BATCH, 1024>>>(ctx_out);
}

// round 13
// speedup vs baseline: 1.0806x; 1.0806x over previous
#include <cuda_runtime.h>
#include <cuda_fp16.h>
#include <cstdint>
#include <math.h>

#define BATCH 32
#define SEQ   4096
#define UNITS 1024
#define M_TOTAL (BATCH * SEQ)      // 131072
#define NBLK  8
#define KC    64
#define NCHUNK 16
#define STAGES 3
#define TILE_B 16384               // 128 rows x 128 bytes (fp16, 64 k)
#define STAGE_B (2 * TILE_B)       // Ah, Bh tiles
#define SMEM_GEMM (STAGES * STAGE_B + 2048)   // 100352

// ---------------------------------------------------------------------------
// Scratch
// ---------------------------------------------------------------------------
__device__ __half g_Ah[(size_t)M_TOTAL * UNITS];
__device__ __half g_Bh[(size_t)UNITS * UNITS];     // U_w^T [n][k] fp16
__device__ float g_wsb[BATCH * UNITS];
__device__ float g_score_part[(size_t)M_TOTAL * NBLK];
__device__ float g_ctx_part[BATCH * 8 * UNITS];

// ---------------------------------------------------------------------------
// PTX helpers
// ---------------------------------------------------------------------------
__device__ __forceinline__ uint32_t smem_u32(const void* p) {
    uint32_t a;
    asm("{ .reg .u64 t; cvta.to.shared.u64 t, %1; cvt.u32.u64 %0, t; }" : "=r"(a) : "l"(p));
    return a;
}
__device__ __forceinline__ void cp16(uint32_t dst, const void* src) {
    asm volatile("cp.async.cg.shared.global [%0], [%1], 16;"
                 :: "r"(dst), "l"(__cvta_generic_to_global(src)) : "memory");
}
#define CP_COMMIT() asm volatile("cp.async.commit_group;" ::: "memory")
#define CP_WAIT(n)  asm volatile("cp.async.wait_group %0;" :: "n"(n) : "memory")

__device__ __forceinline__ void ldsm4(uint32_t r[4], uint32_t addr) {
    asm volatile("ldmatrix.sync.aligned.m8n8.x4.shared.b16 {%0,%1,%2,%3}, [%4];"
                 : "=r"(r[0]), "=r"(r[1]), "=r"(r[2]), "=r"(r[3]) : "r"(addr));
}
__device__ __forceinline__ void mma_f16(float c[4], const uint32_t a[4],
                                        uint32_t b0, uint32_t b1) {
    asm volatile(
        "mma.sync.aligned.m16n8k16.row.col.f32.f16.f16.f32 "
        "{%0,%1,%2,%3}, {%4,%5,%6,%7}, {%8,%9}, {%0,%1,%2,%3};"
        : "+f"(c[0]), "+f"(c[1]), "+f"(c[2]), "+f"(c[3])
        : "r"(a[0]), "r"(a[1]), "r"(a[2]), "r"(a[3]), "r"(b0), "r"(b1));
}

// SW128 swizzle: 128x128B tile, (row, 16B-chunk c), c in 0..7
__device__ __forceinline__ uint32_t swz128(int row, int c) {
    return (uint32_t)(row * 128 + ((c ^ (row & 7)) << 4));
}

// fast tanh: 1 - 2/(exp(2x)+1)
__device__ __forceinline__ float ftanh(float x) {
    float e2 = __expf(2.f * x);
    return 1.f - __fdividef(2.f, e2 + 1.f);
}

// ---------------------------------------------------------------------------
// Prep: hidden fp32 -> fp16
// ---------------------------------------------------------------------------
__global__ void convA_kernel(const float* __restrict__ A) {
    size_t i = ((size_t)blockIdx.x * 256 + threadIdx.x) * 8;
    float4 v0 = *(const float4*)(A + i);
    float4 v1 = *(const float4*)(A + i + 4);
    __half h[8];
    float f[8] = {v0.x, v0.y, v0.z, v0.w, v1.x, v1.y, v1.z, v1.w};
    #pragma unroll
    for (int q = 0; q < 8; q++) h[q] = __float2half_rn(f[q]);
    *(uint4*)(g_Ah + i) = *(uint4*)h;
}

// ---------------------------------------------------------------------------
// Prep: U_w [k][n] fp32 -> transposed fp16 [n][k]
// ---------------------------------------------------------------------------
__global__ void convB_kernel(const float* __restrict__ U) {
    __shared__ float t[32][33];
    int n0 = blockIdx.x * 32, k0 = blockIdx.y * 32;
    t[threadIdx.y][threadIdx.x] = U[(size_t)(k0 + threadIdx.y) * UNITS + n0 + threadIdx.x];
    __syncthreads();
    float v = t[threadIdx.x][threadIdx.y];
    g_Bh[(size_t)(n0 + threadIdx.y) * UNITS + k0 + threadIdx.x] = __float2half_rn(v);
}

// ---------------------------------------------------------------------------
// Prep: wsb = s_prev@W_w + W_b + U_b
// ---------------------------------------------------------------------------
__global__ void ws_kernel(const float* __restrict__ s_prev,
                          const float* __restrict__ W_w,
                          const float* __restrict__ W_b,
                          const float* __restrict__ U_b) {
    __shared__ float srow[UNITS];
    int b = blockIdx.x, v = threadIdx.x;
    srow[v] = s_prev[b * UNITS + v];
    __syncthreads();
    float a0 = 0.f, a1 = 0.f, a2 = 0.f, a3 = 0.f;
    #pragma unroll 4
    for (int k = 0; k < UNITS; k += 4) {
        a0 += srow[k + 0] * W_w[(size_t)(k + 0) * UNITS + v];
        a1 += srow[k + 1] * W_w[(size_t)(k + 1) * UNITS + v];
        a2 += srow[k + 2] * W_w[(size_t)(k + 2) * UNITS + v];
        a3 += srow[k + 3] * W_w[(size_t)(k + 3) * UNITS + v];
    }
    g_wsb[b * UNITS + v] = (a0 + a1) + (a2 + a3) + W_b[v] + U_b[v];
}

// ---------------------------------------------------------------------------
// GEMM: 128x128 CTA tile, 8 warps (4m x 2n), warp tile 32x64.
// fp16 single-term, KC=64 chunks, 3-stage cp.async (single incremented
// src pointer, immediate-folded offsets), B-fragment double buffer,
// fast-tanh·V epilogue.  grid = (NBLK, 1024), block = 256, 2 CTAs/SM.
// ---------------------------------------------------------------------------
__global__ __launch_bounds__(256, 2)
void score_gemm_mma(const float* __restrict__ V) {
    extern __shared__ char smem[];
    float* Ws = (float*)(smem + STAGES * STAGE_B);   // [128]
    float* Vs = Ws + 128;                             // [128]
    float (*sc_s)[2] = (float(*)[2])(Vs + 128);       // [128][2]

    const int nt    = blockIdx.x;
    const int mtile = blockIdx.y;
    const int tid   = threadIdx.x;
    const int lane  = tid & 31;
    const int wid   = tid >> 5;
    const int wm    = wid & 3;           // m quarter (32 rows)
    const int wn    = wid >> 2;          // n half (64 cols)
    const int b     = mtile >> 5;
    const uint32_t sbase = smem_u32(smem);

    if (tid < 128) {
        Ws[tid] = g_wsb[b * UNITS + nt * 128 + tid];
        Vs[tid] = V[nt * 128 + tid];
    }

    float acc[2][8][4];
    #pragma unroll
    for (int mi = 0; mi < 2; mi++)
        #pragma unroll
        for (int nf = 0; nf < 8; nf++)
            #pragma unroll
            for (int q = 0; q < 4; q++)
                acc[mi][nf][q] = 0.f;

    // --- cp.async geometry: ONE A ptr + ONE B ptr, j-offsets are constants ---
    // seg j: row = row0 + 32*j  ->  src + j*32*UNITS, dst + j*4096 (swz-invariant)
    const int row0 = tid >> 3, c0 = tid & 7;
    const uint32_t cp_d0 = swz128(row0, c0);
    const __half* cpA = g_Ah + (size_t)mtile * 128 * UNITS + (size_t)row0 * UNITS + c0 * 8;
    const __half* cpB = g_Bh + (size_t)nt    * 128 * UNITS + (size_t)row0 * UNITS + c0 * 8;

    // --- ldsm fragment bases; XOR factor shared across frags ---
    const int a_row_off = ((lane >> 3) & 1) * 8 + (lane & 7);
    const int k_sub     = lane >> 4;          // 0/1
    const int b_row_off = lane & 15;
    const int r7a = a_row_off & 7;
    const int r7b = b_row_off & 7;
    uint32_t rbA[2], rbB[4];
    #pragma unroll
    for (int mi = 0; mi < 2; mi++)
        rbA[mi] = (uint32_t)((wm * 32 + mi * 16 + a_row_off) * 128);
    #pragma unroll
    for (int p = 0; p < 4; p++)
        rbB[p] = (uint32_t)(TILE_B + (wn * 64 + p * 16 + b_row_off) * 128);

    // prologue: 2 stages in flight (chunks 0, 1)
    #pragma unroll
    for (int st0 = 0; st0 < 2; st0++) {
        uint32_t sb = sbase + st0 * STAGE_B + cp_d0;
        #pragma unroll
        for (int j = 0; j < 4; j++) {
            cp16(sb + j * 4096,          cpA + j * (32 * UNITS) + st0 * KC);
            cp16(sb + TILE_B + j * 4096, cpB + j * (32 * UNITS) + st0 * KC);
        }
        CP_COMMIT();
    }

    int cons = 0, prod = 2;
    for (int kc = 0; kc < NCHUNK; kc++) {
        CP_WAIT(1);
        __syncthreads();
        if (kc + 2 < NCHUNK) {
            uint32_t sb = sbase + prod * STAGE_B + cp_d0;
            #pragma unroll
            for (int j = 0; j < 4; j++) {
                cp16(sb + j * 4096,          cpA + j * (32 * UNITS) + 2 * KC);
                cp16(sb + TILE_B + j * 4096, cpB + j * (32 * UNITS) + 2 * KC);
            }
        }
        CP_COMMIT();
        cpA += KC; cpB += KC;

        const uint32_t st = sbase + cons * STAGE_B;
        const uint32_t aAddr0 = st + rbA[0], aAddr1 = st + rbA[1];
        const uint32_t bA0 = st + rbB[0], bA1 = st + rbB[1];
        const uint32_t bA2 = st + rbB[2], bA3 = st + rbB[3];

        // B-fragment double buffer: bb[par] holds the frag being consumed,
        // bb[par^1] is being loaded one slot ahead.
        uint32_t a[2][4], bb[2][4];
        {   // preload (ks0, p0)
            const uint32_t xB0 = (uint32_t)((k_sub ^ r7b) << 4);
            ldsm4(bb[0], bA0 + xB0);
        }
        #pragma unroll
        for (int ks = 0; ks < 4; ks++) {
            const int kk = (ks << 1) | k_sub;
            const uint32_t xA  = (uint32_t)((kk ^ r7a) << 4);
            const uint32_t xB  = (uint32_t)((kk ^ r7b) << 4);
            const uint32_t xBn = (uint32_t)(((kk + 2) ^ r7b) << 4);  // next ks

            ldsm4(a[0], aAddr0 + xA);
            ldsm4(a[1], aAddr1 + xA);

            // p0: prefetch p1, consume bb[0]
            ldsm4(bb[1], bA1 + xB);
            mma_f16(acc[0][0], a[0], bb[0][0], bb[0][2]);
            mma_f16(acc[0][1], a[0], bb[0][1], bb[0][3]);
            mma_f16(acc[1][0], a[1], bb[0][0], bb[0][2]);
            mma_f16(acc[1][1], a[1], bb[0][1], bb[0][3]);
            // p1: prefetch p2, consume bb[1]
            ldsm4(bb[0], bA2 + xB);
            mma_f16(acc[0][2], a[0], bb[1][0], bb[1][2]);
            mma_f16(acc[0][3], a[0], bb[1][1], bb[1][3]);
            mma_f16(acc[1][2], a[1], bb[1][0], bb[1][2]);
            mma_f16(acc[1][3], a[1], bb[1][1], bb[1][3]);
            // p2: prefetch p3, consume bb[0]
            ldsm4(bb[1], bA3 + xB);
            mma_f16(acc[0][4], a[0], bb[0][0], bb[0][2]);
            mma_f16(acc[0][5], a[0], bb[0][1], bb[0][3]);
            mma_f16(acc[1][4], a[1], bb[0][0], bb[0][2]);
            mma_f16(acc[1][5], a[1], bb[0][1], bb[0][3]);
            // p3: prefetch next ks's p0 (if any), consume bb[1]
            if (ks < 3) ldsm4(bb[0], bA0 + xBn);
            mma_f16(acc[0][6], a[0], bb[1][0], bb[1][2]);
            mma_f16(acc[0][7], a[0], bb[1][1], bb[1][3]);
            mma_f16(acc[1][6], a[1], bb[1][0], bb[1][2]);
            mma_f16(acc[1][7], a[1], bb[1][1], bb[1][3]);
        }
        cons = (cons == 2) ? 0 : cons + 1;
        prod = (prod == 2) ? 0 : prod + 1;
    }

    // ---- epilogue ----
    const int tc = (lane & 3) * 2;
    #pragma unroll
    for (int mi = 0; mi < 2; mi++) {
        float s0 = 0.f, s1 = 0.f;
        #pragma unroll
        for (int nf = 0; nf < 8; nf++) {
            int n = wn * 64 + nf * 8 + tc;
            float w0 = Ws[n], w1 = Ws[n + 1];
            float v0 = Vs[n], v1 = Vs[n + 1];
            s0 += v0 * ftanh(w0 + acc[mi][nf][0]) + v1 * ftanh(w1 + acc[mi][nf][1]);
            s1 += v0 * ftanh(w0 + acc[mi][nf][2]) + v1 * ftanh(w1 + acc[mi][nf][3]);
        }
        s0 += __shfl_xor_sync(0xffffffffu, s0, 1);
        s0 += __shfl_xor_sync(0xffffffffu, s0, 2);
        s1 += __shfl_xor_sync(0xffffffffu, s1, 1);
        s1 += __shfl_xor_sync(0xffffffffu, s1, 2);
        if ((lane & 3) == 0) {
            int r = wm * 32 + mi * 16 + (lane >> 2);
            sc_s[r][wn]     = s0;
            sc_s[r + 8][wn] = s1;
        }
    }
    __syncthreads();
    if (tid < 128)
        g_score_part[((size_t)mtile * 128 + tid) * NBLK + nt] =
            sc_s[tid][0] + sc_s[tid][1];
}

// ---------------------------------------------------------------------------
// Softmax (sums NBLK partials + V_b), writes weights.
// ---------------------------------------------------------------------------
__global__ void softmax_kernel(float* __restrict__ weights_out,
                               const float* __restrict__ V_b) {
    __shared__ float red[1024];
    const int b = blockIdx.x, t = threadIdx.x;
    const float vb = V_b[0];

    float sc[4];
    float mx = -1e30f;
    #pragma unroll
    for (int j = 0; j < 4; j++) {
        int s = t + j * 1024;
        const float* p = &g_score_part[(size_t)(b * SEQ + s) * NBLK];
        float v = vb;
        #pragma unroll
        for (int q = 0; q < NBLK; q++) v += p[q];
        sc[j] = v;
        mx = fmaxf(mx, v);
    }
    red[t] = mx;
    __syncthreads();
    for (int o = 512; o > 0; o >>= 1) {
        if (t < o) red[t] = fmaxf(red[t], red[t + o]);
        __syncthreads();
    }
    mx = red[0];
    __syncthreads();

    float e[4], sum = 0.f;
    #pragma unroll
    for (int j = 0; j < 4; j++) { e[j] = expf(sc[j] - mx); sum += e[j]; }
    red[t] = sum;
    __syncthreads();
    for (int o = 512; o > 0; o >>= 1) {
        if (t < o) red[t] += red[t + o];
        __syncthreads();
    }
    float inv = 1.f / red[0];
    #pragma unroll
    for (int j = 0; j < 4; j++)
        weights_out[b * SEQ + t + j * 1024] = e[j] * inv;
}

// ---------------------------------------------------------------------------
// Context: weighted sum over S, reading fp16 g_Ah.
// ---------------------------------------------------------------------------
__global__ void ctx_partial_kernel(const float* __restrict__ W) {
    const int b = blockIdx.x, cs = blockIdx.y, u = threadIdx.x;
    const float* w = W + b * SEQ + cs * 512;
    const __half* h = g_Ah + ((size_t)b * SEQ + cs * 512) * UNITS + u;
    float a0 = 0.f, a1 = 0.f, a2 = 0.f, a3 = 0.f;
    for (int s = 0; s < 512; s += 4) {
        a0 += w[s + 0] * __half2float(h[(size_t)(s + 0) * UNITS]);
        a1 += w[s + 1] * __half2float(h[(size_t)(s + 1) * UNITS]);
        a2 += w[s + 2] * __half2float(h[(size_t)(s + 2) * UNITS]);
        a3 += w[s + 3] * __half2float(h[(size_t)(s + 3) * UNITS]);
    }
    g_ctx_part[(b * 8 + cs) * UNITS + u] = (a0 + a1) + (a2 + a3);
}

__global__ void ctx_reduce_kernel(float* __restrict__ ctx_out) {
    const int b = blockIdx.x, u = threadIdx.x;
    float acc = 0.f;
    #pragma unroll
    for (int cs = 0; cs < 8; cs++)
        acc += g_ctx_part[(b * 8 + cs) * UNITS + u];
    ctx_out[b * UNITS + u] = acc;
}

// ---------------------------------------------------------------------------
extern "C" void kernel_launch(void* const* d_in, const int* in_sizes, int n_in,
                              void* d_out, int out_size) {
    const float* s_prev = (const float*)d_in[0];
    const float* hidden = (const float*)d_in[1];
    const float* W_w    = (const float*)d_in[2];
    const float* W_b    = (const float*)d_in[3];
    const float* U_w    = (const float*)d_in[4];
    const float* U_b    = (const float*)d_in[5];
    const float* V_w    = (const float*)d_in[6];
    const float* V_b    = (const float*)d_in[7];

    float* out     = (float*)d_out;
    float* ctx_out = out;                      // [32,1024]
    float* w_out   = out + BATCH * UNITS;      // [32,4096,1]

    cudaFuncSetAttribute(score_gemm_mma,
        cudaFuncAttributeMaxDynamicSharedMemorySize, SMEM_GEMM);

    convA_kernel<<<(unsigned)((size_t)M_TOTAL * UNITS / 2048), 256>>>(hidden);
    convB_kernel<<<dim3(32, 32), dim3(32, 32)>>>(U_w);
    ws_kernel<<<BATCH, UNITS>>>(s_prev, W_w, W_b, U_b);
    score_gemm_mma<<<dim3(NBLK, M_TOTAL / 128), 256, SMEM_GEMM>>>(V_w);
    softmax_kernel<<<BATCH, 1024>>>(w_out, V_b);
    ctx_partial_kernel<<<dim3(BATCH, 8), 1024>>>(w_out);
    ctx_reduce_kernel<<<BATCH, 1024>>>(ctx_out);
}

// round 14
// speedup vs baseline: 1.0909x; 1.0095x over previous
#include <cuda_runtime.h>
#include <cuda_fp16.h>
#include <cstdint>
#include <math.h>

#define BATCH 32
#define SEQ   4096
#define UNITS 1024
#define M_TOTAL (BATCH * SEQ)      // 131072
#define NBLK  8
#define KC    64
#define NCHUNK 16
#define STAGES 3
#define TILE_B 16384               // 128 rows x 128 bytes (fp16, 64 k)
#define STAGE_B (2 * TILE_B)       // Ah, Bh tiles
#define SMEM_GEMM (STAGES * STAGE_B + 2048)   // 100352

// ---------------------------------------------------------------------------
// Scratch
// ---------------------------------------------------------------------------
__device__ __half g_Ah[(size_t)M_TOTAL * UNITS];
__device__ __half g_Bh[(size_t)UNITS * UNITS];     // U_w^T [n][k] fp16
__device__ float g_wsb[BATCH * UNITS];
__device__ float g_score_part[(size_t)M_TOTAL * NBLK];
__device__ float g_ctx_part[BATCH * 8 * UNITS];

// ---------------------------------------------------------------------------
// PTX helpers
// ---------------------------------------------------------------------------
__device__ __forceinline__ uint32_t smem_u32(const void* p) {
    uint32_t a;
    asm("{ .reg .u64 t; cvta.to.shared.u64 t, %1; cvt.u32.u64 %0, t; }" : "=r"(a) : "l"(p));
    return a;
}
__device__ __forceinline__ void cp16(uint32_t dst, const void* src) {
    asm volatile("cp.async.cg.shared.global [%0], [%1], 16;"
                 :: "r"(dst), "l"(__cvta_generic_to_global(src)) : "memory");
}
#define CP_COMMIT() asm volatile("cp.async.commit_group;" ::: "memory")
#define CP_WAIT(n)  asm volatile("cp.async.wait_group %0;" :: "n"(n) : "memory")

__device__ __forceinline__ void ldsm4(uint32_t r[4], uint32_t addr) {
    asm volatile("ldmatrix.sync.aligned.m8n8.x4.shared.b16 {%0,%1,%2,%3}, [%4];"
                 : "=r"(r[0]), "=r"(r[1]), "=r"(r[2]), "=r"(r[3]) : "r"(addr));
}
__device__ __forceinline__ void mma_f16(float c[4], const uint32_t a[4],
                                        uint32_t b0, uint32_t b1) {
    asm volatile(
        "mma.sync.aligned.m16n8k16.row.col.f32.f16.f16.f32 "
        "{%0,%1,%2,%3}, {%4,%5,%6,%7}, {%8,%9}, {%0,%1,%2,%3};"
        : "+f"(c[0]), "+f"(c[1]), "+f"(c[2]), "+f"(c[3])
        : "r"(a[0]), "r"(a[1]), "r"(a[2]), "r"(a[3]), "r"(b0), "r"(b1));
}

// SW128 swizzle: 128x128B tile, (row, 16B-chunk c), c in 0..7
__device__ __forceinline__ uint32_t swz128(int row, int c) {
    return (uint32_t)(row * 128 + ((c ^ (row & 7)) << 4));
}

// fast tanh: 1 - 2/(exp(2x)+1)
__device__ __forceinline__ float ftanh(float x) {
    float e2 = __expf(2.f * x);
    return 1.f - __fdividef(2.f, e2 + 1.f);
}

// ---------------------------------------------------------------------------
// Prep: hidden fp32 -> fp16
// ---------------------------------------------------------------------------
__global__ void convA_kernel(const float* __restrict__ A) {
    size_t i = ((size_t)blockIdx.x * 256 + threadIdx.x) * 8;
    float4 v0 = *(const float4*)(A + i);
    float4 v1 = *(const float4*)(A + i + 4);
    __half h[8];
    float f[8] = {v0.x, v0.y, v0.z, v0.w, v1.x, v1.y, v1.z, v1.w};
    #pragma unroll
    for (int q = 0; q < 8; q++) h[q] = __float2half_rn(f[q]);
    *(uint4*)(g_Ah + i) = *(uint4*)h;
}

// ---------------------------------------------------------------------------
// Prep: U_w [k][n] fp32 -> transposed fp16 [n][k]
// ---------------------------------------------------------------------------
__global__ void convB_kernel(const float* __restrict__ U) {
    __shared__ float t[32][33];
    int n0 = blockIdx.x * 32, k0 = blockIdx.y * 32;
    t[threadIdx.y][threadIdx.x] = U[(size_t)(k0 + threadIdx.y) * UNITS + n0 + threadIdx.x];
    __syncthreads();
    float v = t[threadIdx.x][threadIdx.y];
    g_Bh[(size_t)(n0 + threadIdx.y) * UNITS + k0 + threadIdx.x] = __float2half_rn(v);
}

// ---------------------------------------------------------------------------
// Prep: wsb = s_prev@W_w + W_b + U_b
// ---------------------------------------------------------------------------
__global__ void ws_kernel(const float* __restrict__ s_prev,
                          const float* __restrict__ W_w,
                          const float* __restrict__ W_b,
                          const float* __restrict__ U_b) {
    __shared__ float srow[UNITS];
    int b = blockIdx.x, v = threadIdx.x;
    srow[v] = s_prev[b * UNITS + v];
    __syncthreads();
    float a0 = 0.f, a1 = 0.f, a2 = 0.f, a3 = 0.f;
    #pragma unroll 4
    for (int k = 0; k < UNITS; k += 4) {
        a0 += srow[k + 0] * W_w[(size_t)(k + 0) * UNITS + v];
        a1 += srow[k + 1] * W_w[(size_t)(k + 1) * UNITS + v];
        a2 += srow[k + 2] * W_w[(size_t)(k + 2) * UNITS + v];
        a3 += srow[k + 3] * W_w[(size_t)(k + 3) * UNITS + v];
    }
    g_wsb[b * UNITS + v] = (a0 + a1) + (a2 + a3) + W_b[v] + U_b[v];
}

// ---------------------------------------------------------------------------
// GEMM: 128x128 CTA tile, 8 warps (4m x 2n), warp tile 32x64.
// fp16 single-term, KC=64 chunks, 3-stage cp.async, A- and B-fragment
// double buffers, fast-tanh·V epilogue.
// grid = (NBLK, 1024), block = 256, 2 CTAs/SM.
// ---------------------------------------------------------------------------
__global__ __launch_bounds__(256, 2)
void score_gemm_mma(const float* __restrict__ V) {
    extern __shared__ char smem[];
    float* Ws = (float*)(smem + STAGES * STAGE_B);   // [128]
    float* Vs = Ws + 128;                             // [128]
    float (*sc_s)[2] = (float(*)[2])(Vs + 128);       // [128][2]

    const int nt    = blockIdx.x;
    const int mtile = blockIdx.y;
    const int tid   = threadIdx.x;
    const int lane  = tid & 31;
    const int wid   = tid >> 5;
    const int wm    = wid & 3;           // m quarter (32 rows)
    const int wn    = wid >> 2;          // n half (64 cols)
    const int b     = mtile >> 5;
    const uint32_t sbase = smem_u32(smem);

    if (tid < 128) {
        Ws[tid] = g_wsb[b * UNITS + nt * 128 + tid];
        Vs[tid] = V[nt * 128 + tid];
    }

    float acc[2][8][4];
    #pragma unroll
    for (int mi = 0; mi < 2; mi++)
        #pragma unroll
        for (int nf = 0; nf < 8; nf++)
            #pragma unroll
            for (int q = 0; q < 4; q++)
                acc[mi][nf][q] = 0.f;

    // --- cp.async geometry: ONE A ptr + ONE B ptr, j-offsets constants ---
    const int row0 = tid >> 3, c0 = tid & 7;
    const uint32_t cp_d0 = swz128(row0, c0);
    const __half* cpA = g_Ah + (size_t)mtile * 128 * UNITS + (size_t)row0 * UNITS + c0 * 8;
    const __half* cpB = g_Bh + (size_t)nt    * 128 * UNITS + (size_t)row0 * UNITS + c0 * 8;

    // --- ldsm fragment bases; XOR factor shared across frags ---
    const int a_row_off = ((lane >> 3) & 1) * 8 + (lane & 7);
    const int k_sub     = lane >> 4;          // 0/1
    const int b_row_off = lane & 15;
    const int r7a = a_row_off & 7;
    const int r7b = b_row_off & 7;
    uint32_t rbA[2], rbB[4];
    #pragma unroll
    for (int mi = 0; mi < 2; mi++)
        rbA[mi] = (uint32_t)((wm * 32 + mi * 16 + a_row_off) * 128);
    #pragma unroll
    for (int p = 0; p < 4; p++)
        rbB[p] = (uint32_t)(TILE_B + (wn * 64 + p * 16 + b_row_off) * 128);

    // prologue: 2 stages in flight (chunks 0, 1)
    #pragma unroll
    for (int st0 = 0; st0 < 2; st0++) {
        uint32_t sb = sbase + st0 * STAGE_B + cp_d0;
        #pragma unroll
        for (int j = 0; j < 4; j++) {
            cp16(sb + j * 4096,          cpA + j * (32 * UNITS) + st0 * KC);
            cp16(sb + TILE_B + j * 4096, cpB + j * (32 * UNITS) + st0 * KC);
        }
        CP_COMMIT();
    }

    int cons = 0, prod = 2;
    for (int kc = 0; kc < NCHUNK; kc++) {
        CP_WAIT(1);
        __syncthreads();
        if (kc + 2 < NCHUNK) {
            uint32_t sb = sbase + prod * STAGE_B + cp_d0;
            #pragma unroll
            for (int j = 0; j < 4; j++) {
                cp16(sb + j * 4096,          cpA + j * (32 * UNITS) + 2 * KC);
                cp16(sb + TILE_B + j * 4096, cpB + j * (32 * UNITS) + 2 * KC);
            }
        }
        CP_COMMIT();
        cpA += KC; cpB += KC;

        const uint32_t st = sbase + cons * STAGE_B;
        const uint32_t aAddr0 = st + rbA[0], aAddr1 = st + rbA[1];
        const uint32_t bA0 = st + rbB[0], bA1 = st + rbB[1];
        const uint32_t bA2 = st + rbB[2], bA3 = st + rbB[3];

        // A- and B-fragment double buffers
        uint32_t a[2][2][4], bb[2][4];
        {   // preload A for ks0 and B (ks0, p0)
            const uint32_t xA0 = (uint32_t)((k_sub ^ r7a) << 4);
            ldsm4(a[0][0], aAddr0 + xA0);
            ldsm4(a[0][1], aAddr1 + xA0);
            ldsm4(bb[0], bA0 + (uint32_t)((k_sub ^ r7b) << 4));
        }
        #pragma unroll
        for (int ks = 0; ks < 4; ks++) {
            const int par = ks & 1;
            const int kk  = (ks << 1) | k_sub;
            const uint32_t xB  = (uint32_t)((kk ^ r7b) << 4);
            const uint32_t xBn = (uint32_t)(((kk + 2) ^ r7b) << 4);   // next ks
            const uint32_t xAn = (uint32_t)(((kk + 2) ^ r7a) << 4);

            // prefetch next ks's A fragments
            if (ks < 3) {
                ldsm4(a[par ^ 1][0], aAddr0 + xAn);
                ldsm4(a[par ^ 1][1], aAddr1 + xAn);
            }

            // p0: prefetch p1, consume bb[0]
            ldsm4(bb[1], bA1 + xB);
            mma_f16(acc[0][0], a[par][0], bb[0][0], bb[0][2]);
            mma_f16(acc[0][1], a[par][0], bb[0][1], bb[0][3]);
            mma_f16(acc[1][0], a[par][1], bb[0][0], bb[0][2]);
            mma_f16(acc[1][1], a[par][1], bb[0][1], bb[0][3]);
            // p1: prefetch p2, consume bb[1]
            ldsm4(bb[0], bA2 + xB);
            mma_f16(acc[0][2], a[par][0], bb[1][0], bb[1][2]);
            mma_f16(acc[0][3], a[par][0], bb[1][1], bb[1][3]);
            mma_f16(acc[1][2], a[par][1], bb[1][0], bb[1][2]);
            mma_f16(acc[1][3], a[par][1], bb[1][1], bb[1][3]);
            // p2: prefetch p3, consume bb[0]
            ldsm4(bb[1], bA3 + xB);
            mma_f16(acc[0][4], a[par][0], bb[0][0], bb[0][2]);
            mma_f16(acc[0][5], a[par][0], bb[0][1], bb[0][3]);
            mma_f16(acc[1][4], a[par][1], bb[0][0], bb[0][2]);
            mma_f16(acc[1][5], a[par][1], bb[0][1], bb[0][3]);
            // p3: prefetch next ks's p0, consume bb[1]
            if (ks < 3) ldsm4(bb[0], bA0 + xBn);
            mma_f16(acc[0][6], a[par][0], bb[1][0], bb[1][2]);
            mma_f16(acc[0][7], a[par][0], bb[1][1], bb[1][3]);
            mma_f16(acc[1][6], a[par][1], bb[1][0], bb[1][2]);
            mma_f16(acc[1][7], a[par][1], bb[1][1], bb[1][3]);
        }
        cons = (cons == 2) ? 0 : cons + 1;
        prod = (prod == 2) ? 0 : prod + 1;
    }

    // ---- epilogue ----
    const int tc = (lane & 3) * 2;
    #pragma unroll
    for (int mi = 0; mi < 2; mi++) {
        float s0 = 0.f, s1 = 0.f;
        #pragma unroll
        for (int nf = 0; nf < 8; nf++) {
            int n = wn * 64 + nf * 8 + tc;
            float w0 = Ws[n], w1 = Ws[n + 1];
            float v0 = Vs[n], v1 = Vs[n + 1];
            s0 += v0 * ftanh(w0 + acc[mi][nf][0]) + v1 * ftanh(w1 + acc[mi][nf][1]);
            s1 += v0 * ftanh(w0 + acc[mi][nf][2]) + v1 * ftanh(w1 + acc[mi][nf][3]);
        }
        s0 += __shfl_xor_sync(0xffffffffu, s0, 1);
        s0 += __shfl_xor_sync(0xffffffffu, s0, 2);
        s1 += __shfl_xor_sync(0xffffffffu, s1, 1);
        s1 += __shfl_xor_sync(0xffffffffu, s1, 2);
        if ((lane & 3) == 0) {
            int r = wm * 32 + mi * 16 + (lane >> 2);
            sc_s[r][wn]     = s0;
            sc_s[r + 8][wn] = s1;
        }
    }
    __syncthreads();
    if (tid < 128)
        g_score_part[((size_t)mtile * 128 + tid) * NBLK + nt] =
            sc_s[tid][0] + sc_s[tid][1];
}

// ---------------------------------------------------------------------------
// Softmax (sums NBLK partials + V_b), writes weights.
// ---------------------------------------------------------------------------
__global__ void softmax_kernel(float* __restrict__ weights_out,
                               const float* __restrict__ V_b) {
    __shared__ float red[1024];
    const int b = blockIdx.x, t = threadIdx.x;
    const float vb = V_b[0];

    float sc[4];
    float mx = -1e30f;
    #pragma unroll
    for (int j = 0; j < 4; j++) {
        int s = t + j * 1024;
        const float* p = &g_score_part[(size_t)(b * SEQ + s) * NBLK];
        float v = vb;
        #pragma unroll
        for (int q = 0; q < NBLK; q++) v += p[q];
        sc[j] = v;
        mx = fmaxf(mx, v);
    }
    red[t] = mx;
    __syncthreads();
    for (int o = 512; o > 0; o >>= 1) {
        if (t < o) red[t] = fmaxf(red[t], red[t + o]);
        __syncthreads();
    }
    mx = red[0];
    __syncthreads();

    float e[4], sum = 0.f;
    #pragma unroll
    for (int j = 0; j < 4; j++) { e[j] = expf(sc[j] - mx); sum += e[j]; }
    red[t] = sum;
    __syncthreads();
    for (int o = 512; o > 0; o >>= 1) {
        if (t < o) red[t] += red[t + o];
        __syncthreads();
    }
    float inv = 1.f / red[0];
    #pragma unroll
    for (int j = 0; j < 4; j++)
        weights_out[b * SEQ + t + j * 1024] = e[j] * inv;
}

// ---------------------------------------------------------------------------
// Context: weighted sum over S, fp16 g_Ah via half2 (block = 512 threads,
// one column-pair per thread).
// ---------------------------------------------------------------------------
__global__ void ctx_partial_kernel(const float* __restrict__ W) {
    const int b = blockIdx.x, cs = blockIdx.y, u2 = threadIdx.x;   // 0..511
    const float* w = W + b * SEQ + cs * 512;
    const __half2* h = (const __half2*)(g_Ah + ((size_t)b * SEQ + cs * 512) * UNITS) + u2;
    float ax = 0.f, ay = 0.f, bx = 0.f, by = 0.f;
    for (int s = 0; s < 512; s += 2) {
        float2 h0 = __half22float2(h[(size_t)(s    ) * 512]);
        float2 h1 = __half22float2(h[(size_t)(s + 1) * 512]);
        float w0 = w[s], w1 = w[s + 1];
        ax += w0 * h0.x; ay += w0 * h0.y;
        bx += w1 * h1.x; by += w1 * h1.y;
    }
    float2* out = (float2*)(g_ctx_part + (b * 8 + cs) * UNITS) + u2;
    *out = make_float2(ax + bx, ay + by);
}

__global__ void ctx_reduce_kernel(float* __restrict__ ctx_out) {
    const int b = blockIdx.x, u = threadIdx.x;
    float acc = 0.f;
    #pragma unroll
    for (int cs = 0; cs < 8; cs++)
        acc += g_ctx_part[(b * 8 + cs) * UNITS + u];
    ctx_out[b * UNITS + u] = acc;
}

// ---------------------------------------------------------------------------
extern "C" void kernel_launch(void* const* d_in, const int* in_sizes, int n_in,
                              void* d_out, int out_size) {
    const float* s_prev = (const float*)d_in[0];
    const float* hidden = (const float*)d_in[1];
    const float* W_w    = (const float*)d_in[2];
    const float* W_b    = (const float*)d_in[3];
    const float* U_w    = (const float*)d_in[4];
    const float* U_b    = (const float*)d_in[5];
    const float* V_w    = (const float*)d_in[6];
    const float* V_b    = (const float*)d_in[7];

    float* out     = (float*)d_out;
    float* ctx_out = out;                      // [32,1024]
    float* w_out   = out + BATCH * UNITS;      // [32,4096,1]

    cudaFuncSetAttribute(score_gemm_mma,
        cudaFuncAttributeMaxDynamicSharedMemorySize, SMEM_GEMM);

    convA_kernel<<<(unsigned)((size_t)M_TOTAL * UNITS / 2048), 256>>>(hidden);
    convB_kernel<<<dim3(32, 32), dim3(32, 32)>>>(U_w);
    ws_kernel<<<BATCH, UNITS>>>(s_prev, W_w, W_b, U_b);
    score_gemm_mma<<<dim3(NBLK, M_TOTAL / 128), 256, SMEM_GEMM>>>(V_w);
    softmax_kernel<<<BATCH, 1024>>>(w_out, V_b);
    ctx_partial_kernel<<<dim3(BATCH, 8), 512>>>(w_out);
    ctx_reduce_kernel<<<BATCH, 1024>>>(ctx_out);
}